// round 4
// baseline (speedup 1.0000x reference)
#include <cuda_runtime.h>
#include <cstdint>

// ---------------- problem constants ----------------
#define BATCH 8
#define IMH 80
#define IMW 80
#define C_ 768
#define NH 12
#define HD 64
#define WIN 14
#define NWIN 6
#define NWINS 36
#define NW 196
#define NTOK (IMH*IMW)
#define MROWS (BATCH*NTOK)   // 51200

// scratch
__device__ float g_qkv[(size_t)MROWS * 3 * C_];
__device__ float g_attn[(size_t)MROWS * C_];
__device__ float g_x32[(size_t)MROWS * C_];
__device__ float g_wqkvT[(size_t)3 * C_ * C_];
__device__ float g_wprojT[(size_t)C_ * C_];

__device__ __forceinline__ float f2tf32f(float f) {
    uint32_t r;
    asm("cvt.rna.tf32.f32 %0, %1;" : "=r"(r) : "f"(f));
    return __uint_as_float(r);
}

// ---------------- prepass kernels ----------------
__global__ void cvt_kernel(const float* __restrict__ in, float* __restrict__ out, int n4)
{
    int i = blockIdx.x * blockDim.x + threadIdx.x;
    for (; i < n4; i += gridDim.x * blockDim.x) {
        float4 v = reinterpret_cast<const float4*>(in)[i];
        v.x = f2tf32f(v.x); v.y = f2tf32f(v.y);
        v.z = f2tf32f(v.z); v.w = f2tf32f(v.w);
        reinterpret_cast<float4*>(out)[i] = v;
    }
}

__global__ void transpose_cvt(const float* __restrict__ in, float* __restrict__ out,
                              int R, int Cc)
{
    __shared__ float tile[32][33];
    int x = blockIdx.x * 32 + threadIdx.x;
    int y0 = blockIdx.y * 32;
#pragma unroll
    for (int j = 0; j < 32; j += 8)
        tile[threadIdx.y + j][threadIdx.x] = in[(size_t)(y0 + threadIdx.y + j) * Cc + x];
    __syncthreads();
    int ox = blockIdx.y * 32 + threadIdx.x;
    int oy0 = blockIdx.x * 32;
#pragma unroll
    for (int j = 0; j < 32; j += 8)
        out[(size_t)(oy0 + threadIdx.y + j) * R + ox] =
            f2tf32f(tile[threadIdx.x][threadIdx.y + j]);
}

// ---------------- tf32 mma GEMM, cp.async + ldmatrix (unchanged from R2) ----------------
#define BK 32
#define LDT 36
#define TILE_FLOATS (128 * LDT)
#define STAGE_FLOATS (2 * TILE_FLOATS)
#define STAGE_BYTES (STAGE_FLOATS * 4)
#define GEMM_SMEM_BYTES (2 * STAGE_BYTES)

__device__ __forceinline__ void cp_async16(uint32_t smem_addr, const float* gptr) {
    asm volatile("cp.async.cg.shared.global [%0], [%1], 16;"
                 :: "r"(smem_addr), "l"(gptr));
}

__global__ void __launch_bounds__(256, 2) gemm_tf32_async(
    const float* __restrict__ A, const float* __restrict__ Bt,
    const float* __restrict__ bias, float* __restrict__ C,
    int M, int N, int K)
{
    extern __shared__ float smem[];
    const uint32_t smem_base = (uint32_t)__cvta_generic_to_shared(smem);

    const int tid  = threadIdx.x;
    const int warp = tid >> 5;
    const int lane = tid & 31;
    const int wm = warp & 1;
    const int wn = warp >> 1;
    const int bm = blockIdx.y * 128;
    const int bn = blockIdx.x * 128;

    const int aRow = wm * 64 + (lane & 15);
    const int aCol = (lane >> 4) * 4;
    const int bRow = wn * 32 + (lane & 7) + ((lane & 16) ? 8 : 0);
    const int bCol = (lane & 8) ? 4 : 0;

    float acc[4][4][4];
#pragma unroll
    for (int i = 0; i < 4; i++)
#pragma unroll
        for (int j = 0; j < 4; j++)
#pragma unroll
            for (int r = 0; r < 4; r++) acc[i][j][r] = 0.f;

    const int NT = K / BK;

    auto issue_stage = [&](int t, int s) {
        const float* Ag = A + (size_t)bm * K + t * BK;
        const float* Bg = Bt + (size_t)bn * K + t * BK;
        uint32_t as = smem_base + s * STAGE_BYTES;
        uint32_t bs = as + TILE_FLOATS * 4;
#pragma unroll
        for (int i = 0; i < 4; i++) {
            int c   = tid + 256 * i;
            int row = c >> 3;
            int kc  = (c & 7) * 4;
            uint32_t doff = (uint32_t)(row * LDT + kc) * 4;
            cp_async16(as + doff, Ag + (size_t)row * K + kc);
            cp_async16(bs + doff, Bg + (size_t)row * K + kc);
        }
        asm volatile("cp.async.commit_group;");
    };

    issue_stage(0, 0);

    for (int t = 0; t < NT; t++) {
        int s = t & 1;
        if (t + 1 < NT) {
            issue_stage(t + 1, (t + 1) & 1);
            asm volatile("cp.async.wait_group 1;");
        } else {
            asm volatile("cp.async.wait_group 0;");
        }
        __syncthreads();

        uint32_t as = smem_base + s * STAGE_BYTES;
        uint32_t bs = as + TILE_FLOATS * 4;

#pragma unroll
        for (int ks = 0; ks < 4; ks++) {
            uint32_t af[4][4];
#pragma unroll
            for (int mi = 0; mi < 4; mi++) {
                uint32_t addr = as + (uint32_t)((aRow + mi * 16) * LDT + aCol + ks * 8) * 4;
                asm volatile("ldmatrix.sync.aligned.m8n8.x4.shared.b16 {%0,%1,%2,%3}, [%4];"
                             : "=r"(af[mi][0]), "=r"(af[mi][1]),
                               "=r"(af[mi][2]), "=r"(af[mi][3])
                             : "r"(addr));
            }
            uint32_t bf[2][4];
#pragma unroll
            for (int np = 0; np < 2; np++) {
                uint32_t addr = bs + (uint32_t)((bRow + np * 16) * LDT + bCol + ks * 8) * 4;
                asm volatile("ldmatrix.sync.aligned.m8n8.x4.shared.b16 {%0,%1,%2,%3}, [%4];"
                             : "=r"(bf[np][0]), "=r"(bf[np][1]),
                               "=r"(bf[np][2]), "=r"(bf[np][3])
                             : "r"(addr));
            }
#pragma unroll
            for (int mi = 0; mi < 4; mi++) {
#pragma unroll
                for (int np = 0; np < 2; np++) {
                    asm volatile(
                        "mma.sync.aligned.m16n8k8.row.col.f32.tf32.tf32.f32 "
                        "{%0,%1,%2,%3}, {%4,%5,%6,%7}, {%8,%9}, {%0,%1,%2,%3};"
                        : "+f"(acc[mi][2*np][0]), "+f"(acc[mi][2*np][1]),
                          "+f"(acc[mi][2*np][2]), "+f"(acc[mi][2*np][3])
                        : "r"(af[mi][0]), "r"(af[mi][1]), "r"(af[mi][2]), "r"(af[mi][3]),
                          "r"(bf[np][0]), "r"(bf[np][1]));
                    asm volatile(
                        "mma.sync.aligned.m16n8k8.row.col.f32.tf32.tf32.f32 "
                        "{%0,%1,%2,%3}, {%4,%5,%6,%7}, {%8,%9}, {%0,%1,%2,%3};"
                        : "+f"(acc[mi][2*np+1][0]), "+f"(acc[mi][2*np+1][1]),
                          "+f"(acc[mi][2*np+1][2]), "+f"(acc[mi][2*np+1][3])
                        : "r"(af[mi][0]), "r"(af[mi][1]), "r"(af[mi][2]), "r"(af[mi][3]),
                          "r"(bf[np][2]), "r"(bf[np][3]));
                }
            }
        }
        __syncthreads();
    }

    const int tg = lane >> 2;
    const int tc = lane & 3;
#pragma unroll
    for (int mi = 0; mi < 4; mi++) {
        int row = bm + wm * 64 + mi * 16 + tg;
#pragma unroll
        for (int ni = 0; ni < 4; ni++) {
            int col = bn + wn * 32 + ni * 8 + tc * 2;
            float b0 = bias ? bias[col]     : 0.f;
            float b1 = bias ? bias[col + 1] : 0.f;
            float2 v0 = make_float2(acc[mi][ni][0] + b0, acc[mi][ni][1] + b1);
            float2 v1 = make_float2(acc[mi][ni][2] + b0, acc[mi][ni][3] + b1);
            *reinterpret_cast<float2*>(&C[(size_t)row * N + col])       = v0;
            *reinterpret_cast<float2*>(&C[(size_t)(row + 8) * N + col]) = v1;
        }
    }
}

// ---------------- tensor-core windowed attention ----------------
// one CTA per (b, window, head); 256 threads / 8 warps; warp w owns 16-row
// query tiles {w, w+8} of the 208-row padded window.
// Q,K smem: [208][68] (tf32, Q pre-scaled); V smem transposed: [64][212].
// Keys processed as 25 n-tiles of 8 (0..199); keys 196..199 masked to -inf.

#define NROWP 208
#define QK_STR 68
#define VT_STR 212
#define ATTN2_FLOATS (2 * NROWP * QK_STR + HD * VT_STR)
#define ATTN2_SMEM_BYTES (ATTN2_FLOATS * 4)   // 167,424

__global__ void __launch_bounds__(256, 1) attn_mma(const float* __restrict__ qkv,
                                                   float* __restrict__ out)
{
    extern __shared__ float sm[];
    float* Qs = sm;                              // [208][68]
    float* Ks = Qs + NROWP * QK_STR;             // [208][68]
    float* VT = Ks + NROWP * QK_STR;             // [64][212]
    const uint32_t smem_u32 = (uint32_t)__cvta_generic_to_shared(sm);
    const uint32_t Koff = NROWP * QK_STR * 4;
    const uint32_t Voff = 2 * NROWP * QK_STR * 4;

    const int bid = blockIdx.x;
    const int h = bid % NH;
    const int l = (bid / NH) % NWINS;
    const int b = bid / (NH * NWINS);
    const int wh = l / NWIN, ww = l % NWIN;

    const int tid  = threadIdx.x;
    const int warp = tid >> 5;
    const int lane = tid & 31;
    const int tg   = lane >> 2;
    const int tc   = lane & 3;

    // ---- gather: tf32-round, scale Q, zero-fill all padding ----
    for (int idx = tid; idx < NROWP * HD; idx += 256) {
        int n = idx >> 6, d = idx & 63;
        float q = 0.f, k = 0.f, v = 0.f;
        if (n < NW) {
            int gh = wh * WIN + (n / WIN);
            int gw = ww * WIN + (n % WIN);
            if (gh < IMH && gw < IMW) {
                size_t off = (size_t)(b * NTOK + gh * IMW + gw) * (3 * C_) + h * HD + d;
                q = qkv[off];
                k = qkv[off + C_];
                v = qkv[off + 2 * C_];
            }
        }
        Qs[n * QK_STR + d] = f2tf32f(q * 0.125f);
        Ks[n * QK_STR + d] = f2tf32f(k);
        VT[d * VT_STR + n] = f2tf32f(v);
    }
    __syncthreads();

    // per-lane ldmatrix address components
    const uint32_t qAddr0 = smem_u32 + (uint32_t)((lane & 15) * QK_STR + (lane >> 4) * 4) * 4;
    const int brow = (lane & 7) + ((lane & 16) ? 8 : 0);
    const int bcol = (lane & 8) ? 4 : 0;
    const uint32_t kAddr0 = smem_u32 + Koff + (uint32_t)(brow * QK_STR + bcol) * 4;
    const uint32_t vAddr0 = smem_u32 + Voff + (uint32_t)(brow * VT_STR + bcol) * 4;

#pragma unroll 1
    for (int tt = 0; tt < 2; tt++) {
        const int tile = warp + tt * 8;
        if (tile > 12) break;

        // ---- S = Q_tile @ K^T : acc[25 n-tiles][4] ----
        float acc[25][4];
#pragma unroll
        for (int j = 0; j < 25; j++)
#pragma unroll
            for (int r = 0; r < 4; r++) acc[j][r] = 0.f;

        uint32_t qa[8][4];
#pragma unroll
        for (int ks = 0; ks < 8; ks++) {
            uint32_t addr = qAddr0 + (uint32_t)(tile * 16 * QK_STR) * 4 + ks * 32;
            asm volatile("ldmatrix.sync.aligned.m8n8.x4.shared.b16 {%0,%1,%2,%3}, [%4];"
                         : "=r"(qa[ks][0]), "=r"(qa[ks][1]),
                           "=r"(qa[ks][2]), "=r"(qa[ks][3]) : "r"(addr));
        }

#pragma unroll
        for (int ks = 0; ks < 8; ks++) {
#pragma unroll
            for (int np = 0; np < 13; np++) {
                uint32_t kb[4];
                uint32_t addr = kAddr0 + (uint32_t)(np * 16 * QK_STR) * 4 + ks * 32;
                asm volatile("ldmatrix.sync.aligned.m8n8.x4.shared.b16 {%0,%1,%2,%3}, [%4];"
                             : "=r"(kb[0]), "=r"(kb[1]), "=r"(kb[2]), "=r"(kb[3])
                             : "r"(addr));
                asm volatile(
                    "mma.sync.aligned.m16n8k8.row.col.f32.tf32.tf32.f32 "
                    "{%0,%1,%2,%3}, {%4,%5,%6,%7}, {%8,%9}, {%0,%1,%2,%3};"
                    : "+f"(acc[2*np][0]), "+f"(acc[2*np][1]),
                      "+f"(acc[2*np][2]), "+f"(acc[2*np][3])
                    : "r"(qa[ks][0]), "r"(qa[ks][1]), "r"(qa[ks][2]), "r"(qa[ks][3]),
                      "r"(kb[0]), "r"(kb[1]));
                if (2 * np + 1 < 25) {
                    asm volatile(
                        "mma.sync.aligned.m16n8k8.row.col.f32.tf32.tf32.f32 "
                        "{%0,%1,%2,%3}, {%4,%5,%6,%7}, {%8,%9}, {%0,%1,%2,%3};"
                        : "+f"(acc[2*np+1][0]), "+f"(acc[2*np+1][1]),
                          "+f"(acc[2*np+1][2]), "+f"(acc[2*np+1][3])
                        : "r"(qa[ks][0]), "r"(qa[ks][1]), "r"(qa[ks][2]), "r"(qa[ks][3]),
                          "r"(kb[2]), "r"(kb[3]));
                }
            }
        }

        // ---- mask pad keys 196..199 (n-tile 24, cols >= 4) ----
        if (tc >= 2) {
            acc[24][0] = acc[24][1] = acc[24][2] = acc[24][3] = -1e30f;
        }

        // ---- softmax (unnormalized; rowsum applied at output) ----
        float mL = -1e30f, mH = -1e30f;
#pragma unroll
        for (int j = 0; j < 25; j++) {
            mL = fmaxf(mL, fmaxf(acc[j][0], acc[j][1]));
            mH = fmaxf(mH, fmaxf(acc[j][2], acc[j][3]));
        }
        mL = fmaxf(mL, __shfl_xor_sync(0xffffffffu, mL, 1));
        mL = fmaxf(mL, __shfl_xor_sync(0xffffffffu, mL, 2));
        mH = fmaxf(mH, __shfl_xor_sync(0xffffffffu, mH, 1));
        mH = fmaxf(mH, __shfl_xor_sync(0xffffffffu, mH, 2));

        float sL = 0.f, sH = 0.f;
#pragma unroll
        for (int j = 0; j < 25; j++) {
            float e0 = __expf(acc[j][0] - mL);
            float e1 = __expf(acc[j][1] - mL);
            float e2 = __expf(acc[j][2] - mH);
            float e3 = __expf(acc[j][3] - mH);
            sL += e0 + e1;
            sH += e2 + e3;
            acc[j][0] = f2tf32f(e0);
            acc[j][1] = f2tf32f(e1);
            acc[j][2] = f2tf32f(e2);
            acc[j][3] = f2tf32f(e3);
        }
        sL += __shfl_xor_sync(0xffffffffu, sL, 1);
        sL += __shfl_xor_sync(0xffffffffu, sL, 2);
        sH += __shfl_xor_sync(0xffffffffu, sH, 1);
        sH += __shfl_xor_sync(0xffffffffu, sH, 2);

        // ---- O = P @ V : acc -> A-fragments via shuffles ----
        float o[8][4];
#pragma unroll
        for (int n = 0; n < 8; n++)
#pragma unroll
            for (int r = 0; r < 4; r++) o[n][r] = 0.f;

        const int src  = (lane & ~3) | (tc >> 1);
        const bool odd = (tc & 1);

#pragma unroll
        for (int kt = 0; kt < 25; kt++) {
            float x0 = __shfl_sync(0xffffffffu, acc[kt][0], src);
            float x1 = __shfl_sync(0xffffffffu, acc[kt][1], src);
            float y0 = __shfl_sync(0xffffffffu, acc[kt][0], src + 2);
            float y1 = __shfl_sync(0xffffffffu, acc[kt][1], src + 2);
            float z0 = __shfl_sync(0xffffffffu, acc[kt][2], src);
            float z1 = __shfl_sync(0xffffffffu, acc[kt][3], src);
            float w0 = __shfl_sync(0xffffffffu, acc[kt][2], src + 2);
            float w1 = __shfl_sync(0xffffffffu, acc[kt][3], src + 2);
            uint32_t a0 = __float_as_uint(odd ? x1 : x0);
            uint32_t a1 = __float_as_uint(odd ? z1 : z0);
            uint32_t a2 = __float_as_uint(odd ? y1 : y0);
            uint32_t a3 = __float_as_uint(odd ? w1 : w0);
            // note: z uses acc[kt][2]/[3] shfl'd from src; w from src+2 — rows tg+8
#pragma unroll
            for (int np = 0; np < 4; np++) {
                uint32_t vb[4];
                uint32_t addr = vAddr0 + (uint32_t)(np * 16 * VT_STR) * 4 + kt * 32;
                asm volatile("ldmatrix.sync.aligned.m8n8.x4.shared.b16 {%0,%1,%2,%3}, [%4];"
                             : "=r"(vb[0]), "=r"(vb[1]), "=r"(vb[2]), "=r"(vb[3])
                             : "r"(addr));
                asm volatile(
                    "mma.sync.aligned.m16n8k8.row.col.f32.tf32.tf32.f32 "
                    "{%0,%1,%2,%3}, {%4,%5,%6,%7}, {%8,%9}, {%0,%1,%2,%3};"
                    : "+f"(o[2*np][0]), "+f"(o[2*np][1]),
                      "+f"(o[2*np][2]), "+f"(o[2*np][3])
                    : "r"(a0), "r"(a1), "r"(a2), "r"(a3),
                      "r"(vb[0]), "r"(vb[1]));
                asm volatile(
                    "mma.sync.aligned.m16n8k8.row.col.f32.tf32.tf32.f32 "
                    "{%0,%1,%2,%3}, {%4,%5,%6,%7}, {%8,%9}, {%0,%1,%2,%3};"
                    : "+f"(o[2*np+1][0]), "+f"(o[2*np+1][1]),
                      "+f"(o[2*np+1][2]), "+f"(o[2*np+1][3])
                    : "r"(a0), "r"(a1), "r"(a2), "r"(a3),
                      "r"(vb[2]), "r"(vb[3]));
            }
        }

        // ---- normalize + store (crop to valid tokens) ----
        const float invL = 1.f / sL;
        const float invH = 1.f / sH;
#pragma unroll
        for (int half = 0; half < 2; half++) {
            int n = tile * 16 + tg + half * 8;
            if (n >= NW) continue;
            int gh = wh * WIN + n / WIN;
            int gw = ww * WIN + n % WIN;
            if (gh >= IMH || gw >= IMW) continue;
            size_t off = (size_t)(b * NTOK + gh * IMW + gw) * C_ + h * HD + 2 * tc;
            float inv = half ? invH : invL;
#pragma unroll
            for (int nn = 0; nn < 8; nn++) {
                float2 o2 = make_float2(f2tf32f(o[nn][2*half] * inv),
                                        f2tf32f(o[nn][2*half + 1] * inv));
                *reinterpret_cast<float2*>(&out[off + nn * 8]) = o2;
            }
        }
    }
}

// ---------------- launcher ----------------
extern "C" void kernel_launch(void* const* d_in, const int* in_sizes, int n_in,
                              void* d_out, int out_size)
{
    (void)in_sizes; (void)n_in; (void)out_size;
    const float* x     = (const float*)d_in[0];
    const float* Wqkv  = (const float*)d_in[1];
    const float* Wproj = (const float*)d_in[2];
    const float* bproj = (const float*)d_in[3];
    float* out = (float*)d_out;

    float *qkv, *attn, *x32, *wqkvT, *wprojT;
    cudaGetSymbolAddress((void**)&qkv,    g_qkv);
    cudaGetSymbolAddress((void**)&attn,   g_attn);
    cudaGetSymbolAddress((void**)&x32,    g_x32);
    cudaGetSymbolAddress((void**)&wqkvT,  g_wqkvT);
    cudaGetSymbolAddress((void**)&wprojT, g_wprojT);

    cudaFuncSetAttribute(attn_mma, cudaFuncAttributeMaxDynamicSharedMemorySize,
                         ATTN2_SMEM_BYTES);
    cudaFuncSetAttribute(gemm_tf32_async, cudaFuncAttributeMaxDynamicSharedMemorySize,
                         GEMM_SMEM_BYTES);

    // prepass
    cvt_kernel<<<1184, 256>>>(x, x32, MROWS * C_ / 4);
    {
        dim3 g(3 * C_ / 32, C_ / 32), blk(32, 8);
        transpose_cvt<<<g, blk>>>(Wqkv, wqkvT, C_, 3 * C_);
    }
    {
        dim3 g(C_ / 32, C_ / 32), blk(32, 8);
        transpose_cvt<<<g, blk>>>(Wproj, wprojT, C_, C_);
    }

    // 1) qkv = x @ Wqkv
    {
        dim3 grid(3 * C_ / 128, MROWS / 128);
        gemm_tf32_async<<<grid, 256, GEMM_SMEM_BYTES>>>(x32, wqkvT, nullptr, qkv,
                                                        MROWS, 3 * C_, C_);
    }
    // 2) windowed attention (tensor cores)
    {
        dim3 grid(BATCH * NWINS * NH);
        attn_mma<<<grid, 256, ATTN2_SMEM_BYTES>>>(qkv, attn);
    }
    // 3) out = attn @ Wproj + bproj
    {
        dim3 grid(C_ / 128, MROWS / 128);
        gemm_tf32_async<<<grid, 256, GEMM_SMEM_BYTES>>>(attn, wprojT, bproj, out,
                                                        MROWS, C_, C_);
    }
}

// round 7
// speedup vs baseline: 1.5355x; 1.5355x over previous
#include <cuda_runtime.h>
#include <cstdint>

// ---------------- problem constants ----------------
#define BATCH 8
#define IMH 80
#define IMW 80
#define C_ 768
#define NH 12
#define HD 64
#define WIN 14
#define NWIN 6
#define NWINS 36
#define NW 196
#define NTOK (IMH*IMW)
#define MROWS (BATCH*NTOK)   // 51200

// scratch
__device__ float g_qkv[(size_t)MROWS * 3 * C_];
__device__ float g_attn[(size_t)MROWS * C_];
__device__ float g_x32[(size_t)MROWS * C_];
__device__ float g_wqkvT[(size_t)3 * C_ * C_];
__device__ float g_wprojT[(size_t)C_ * C_];

__device__ __forceinline__ float f2tf32f(float f) {
    uint32_t r;
    asm("cvt.rna.tf32.f32 %0, %1;" : "=r"(r) : "f"(f));
    return __uint_as_float(r);
}

// ---------------- prepass kernels ----------------
__global__ void cvt_kernel(const float* __restrict__ in, float* __restrict__ out, int n4)
{
    int i = blockIdx.x * blockDim.x + threadIdx.x;
    for (; i < n4; i += gridDim.x * blockDim.x) {
        float4 v = reinterpret_cast<const float4*>(in)[i];
        v.x = f2tf32f(v.x); v.y = f2tf32f(v.y);
        v.z = f2tf32f(v.z); v.w = f2tf32f(v.w);
        reinterpret_cast<float4*>(out)[i] = v;
    }
}

__global__ void transpose_cvt(const float* __restrict__ in, float* __restrict__ out,
                              int R, int Cc)
{
    __shared__ float tile[32][33];
    int x = blockIdx.x * 32 + threadIdx.x;
    int y0 = blockIdx.y * 32;
#pragma unroll
    for (int j = 0; j < 32; j += 8)
        tile[threadIdx.y + j][threadIdx.x] = in[(size_t)(y0 + threadIdx.y + j) * Cc + x];
    __syncthreads();
    int ox = blockIdx.y * 32 + threadIdx.x;
    int oy0 = blockIdx.x * 32;
#pragma unroll
    for (int j = 0; j < 32; j += 8)
        out[(size_t)(oy0 + threadIdx.y + j) * R + ox] =
            f2tf32f(tile[threadIdx.x][threadIdx.y + j]);
}

// ---------------- tf32 mma GEMM, cp.async + ldmatrix (unchanged) ----------------
#define BK 32
#define LDT 36
#define TILE_FLOATS (128 * LDT)
#define STAGE_FLOATS (2 * TILE_FLOATS)
#define STAGE_BYTES (STAGE_FLOATS * 4)
#define GEMM_SMEM_BYTES (2 * STAGE_BYTES)

__device__ __forceinline__ void cp_async16(uint32_t smem_addr, const float* gptr) {
    asm volatile("cp.async.cg.shared.global [%0], [%1], 16;"
                 :: "r"(smem_addr), "l"(gptr));
}

__global__ void __launch_bounds__(256, 2) gemm_tf32_async(
    const float* __restrict__ A, const float* __restrict__ Bt,
    const float* __restrict__ bias, float* __restrict__ C,
    int M, int N, int K)
{
    extern __shared__ float smem[];
    const uint32_t smem_base = (uint32_t)__cvta_generic_to_shared(smem);

    const int tid  = threadIdx.x;
    const int warp = tid >> 5;
    const int lane = tid & 31;
    const int wm = warp & 1;
    const int wn = warp >> 1;
    const int bm = blockIdx.y * 128;
    const int bn = blockIdx.x * 128;

    const int aRow = wm * 64 + (lane & 15);
    const int aCol = (lane >> 4) * 4;
    const int bRow = wn * 32 + (lane & 7) + ((lane & 16) ? 8 : 0);
    const int bCol = (lane & 8) ? 4 : 0;

    float acc[4][4][4];
#pragma unroll
    for (int i = 0; i < 4; i++)
#pragma unroll
        for (int j = 0; j < 4; j++)
#pragma unroll
            for (int r = 0; r < 4; r++) acc[i][j][r] = 0.f;

    const int NT = K / BK;

    auto issue_stage = [&](int t, int s) {
        const float* Ag = A + (size_t)bm * K + t * BK;
        const float* Bg = Bt + (size_t)bn * K + t * BK;
        uint32_t as = smem_base + s * STAGE_BYTES;
        uint32_t bs = as + TILE_FLOATS * 4;
#pragma unroll
        for (int i = 0; i < 4; i++) {
            int c   = tid + 256 * i;
            int row = c >> 3;
            int kc  = (c & 7) * 4;
            uint32_t doff = (uint32_t)(row * LDT + kc) * 4;
            cp_async16(as + doff, Ag + (size_t)row * K + kc);
            cp_async16(bs + doff, Bg + (size_t)row * K + kc);
        }
        asm volatile("cp.async.commit_group;");
    };

    issue_stage(0, 0);

    for (int t = 0; t < NT; t++) {
        int s = t & 1;
        if (t + 1 < NT) {
            issue_stage(t + 1, (t + 1) & 1);
            asm volatile("cp.async.wait_group 1;");
        } else {
            asm volatile("cp.async.wait_group 0;");
        }
        __syncthreads();

        uint32_t as = smem_base + s * STAGE_BYTES;
        uint32_t bs = as + TILE_FLOATS * 4;

#pragma unroll
        for (int ks = 0; ks < 4; ks++) {
            uint32_t af[4][4];
#pragma unroll
            for (int mi = 0; mi < 4; mi++) {
                uint32_t addr = as + (uint32_t)((aRow + mi * 16) * LDT + aCol + ks * 8) * 4;
                asm volatile("ldmatrix.sync.aligned.m8n8.x4.shared.b16 {%0,%1,%2,%3}, [%4];"
                             : "=r"(af[mi][0]), "=r"(af[mi][1]),
                               "=r"(af[mi][2]), "=r"(af[mi][3])
                             : "r"(addr));
            }
            uint32_t bf[2][4];
#pragma unroll
            for (int np = 0; np < 2; np++) {
                uint32_t addr = bs + (uint32_t)((bRow + np * 16) * LDT + bCol + ks * 8) * 4;
                asm volatile("ldmatrix.sync.aligned.m8n8.x4.shared.b16 {%0,%1,%2,%3}, [%4];"
                             : "=r"(bf[np][0]), "=r"(bf[np][1]),
                               "=r"(bf[np][2]), "=r"(bf[np][3])
                             : "r"(addr));
            }
#pragma unroll
            for (int mi = 0; mi < 4; mi++) {
#pragma unroll
                for (int np = 0; np < 2; np++) {
                    asm volatile(
                        "mma.sync.aligned.m16n8k8.row.col.f32.tf32.tf32.f32 "
                        "{%0,%1,%2,%3}, {%4,%5,%6,%7}, {%8,%9}, {%0,%1,%2,%3};"
                        : "+f"(acc[mi][2*np][0]), "+f"(acc[mi][2*np][1]),
                          "+f"(acc[mi][2*np][2]), "+f"(acc[mi][2*np][3])
                        : "r"(af[mi][0]), "r"(af[mi][1]), "r"(af[mi][2]), "r"(af[mi][3]),
                          "r"(bf[np][0]), "r"(bf[np][1]));
                    asm volatile(
                        "mma.sync.aligned.m16n8k8.row.col.f32.tf32.tf32.f32 "
                        "{%0,%1,%2,%3}, {%4,%5,%6,%7}, {%8,%9}, {%0,%1,%2,%3};"
                        : "+f"(acc[mi][2*np+1][0]), "+f"(acc[mi][2*np+1][1]),
                          "+f"(acc[mi][2*np+1][2]), "+f"(acc[mi][2*np+1][3])
                        : "r"(af[mi][0]), "r"(af[mi][1]), "r"(af[mi][2]), "r"(af[mi][3]),
                          "r"(bf[np][2]), "r"(bf[np][3]));
                }
            }
        }
        __syncthreads();
    }

    const int tg = lane >> 2;
    const int tc = lane & 3;
#pragma unroll
    for (int mi = 0; mi < 4; mi++) {
        int row = bm + wm * 64 + mi * 16 + tg;
#pragma unroll
        for (int ni = 0; ni < 4; ni++) {
            int col = bn + wn * 32 + ni * 8 + tc * 2;
            float b0 = bias ? bias[col]     : 0.f;
            float b1 = bias ? bias[col + 1] : 0.f;
            float2 v0 = make_float2(acc[mi][ni][0] + b0, acc[mi][ni][1] + b1);
            float2 v1 = make_float2(acc[mi][ni][2] + b0, acc[mi][ni][3] + b1);
            *reinterpret_cast<float2*>(&C[(size_t)row * N + col])       = v0;
            *reinterpret_cast<float2*>(&C[(size_t)(row + 8) * N + col]) = v1;
        }
    }
}

// ---------------- tensor-core windowed attention, v2 ----------------
// one CTA per (b, window, head); 416 threads = 13 warps, one 16-row query tile
// per warp (perfect balance). Keys padded to 224 (28 n-tiles of 8); processed
// in 2 chunks of 14 n-tiles with online softmax (acc = 56 regs, no spills).
// Keys 196..223 masked to -inf; image-zero-pad tokens stay active (reference
// semantics). Q pre-scaled by 1/8.

#define NROWP 224
#define QK_STR 68
#define VT_STR 228
#define ATTN_THREADS 416
#define ATTN2_FLOATS (2 * NROWP * QK_STR + HD * VT_STR)
#define ATTN2_SMEM_BYTES (ATTN2_FLOATS * 4)   // 180224

__global__ void __launch_bounds__(ATTN_THREADS, 1) attn_mma(
    const float* __restrict__ qkv, float* __restrict__ out)
{
    extern __shared__ float sm[];
    float* Qs = sm;                              // [224][68]
    float* Ks = Qs + NROWP * QK_STR;             // [224][68]
    float* VT = Ks + NROWP * QK_STR;             // [64][228]
    const uint32_t smem_u32 = (uint32_t)__cvta_generic_to_shared(sm);
    const uint32_t Koff = NROWP * QK_STR * 4;
    const uint32_t Voff = 2 * NROWP * QK_STR * 4;

    const int bid = blockIdx.x;
    const int h = bid % NH;
    const int l = (bid / NH) % NWINS;
    const int b = bid / (NH * NWINS);
    const int wh = l / NWIN, ww = l % NWIN;

    const int tid  = threadIdx.x;
    const int warp = tid >> 5;        // 0..12 == query tile
    const int lane = tid & 31;
    const int tg   = lane >> 2;
    const int tc   = lane & 3;

    // ---- gather: tf32-round, scale Q, zero-fill all padding ----
    for (int idx = tid; idx < NROWP * HD; idx += ATTN_THREADS) {
        int n = idx >> 6, d = idx & 63;
        float q = 0.f, k = 0.f, v = 0.f;
        if (n < NW) {
            int gh = wh * WIN + (n / WIN);
            int gw = ww * WIN + (n % WIN);
            if (gh < IMH && gw < IMW) {
                size_t off = (size_t)(b * NTOK + gh * IMW + gw) * (3 * C_) + h * HD + d;
                q = qkv[off];
                k = qkv[off + C_];
                v = qkv[off + 2 * C_];
            }
        }
        Qs[n * QK_STR + d] = f2tf32f(q * 0.125f);
        Ks[n * QK_STR + d] = f2tf32f(k);
        VT[d * VT_STR + n] = f2tf32f(v);
    }
    __syncthreads();

    const int tile = warp;

    // per-lane ldmatrix address components
    const uint32_t qAddr0 = smem_u32 +
        (uint32_t)((tile * 16 + (lane & 15)) * QK_STR + (lane >> 4) * 4) * 4;
    const int brow = (lane & 7) + ((lane & 16) ? 8 : 0);
    const int bcol = (lane & 8) ? 4 : 0;
    const uint32_t kAddr0 = smem_u32 + Koff + (uint32_t)(brow * QK_STR + bcol) * 4;
    const uint32_t vAddr0 = smem_u32 + Voff + (uint32_t)(brow * VT_STR + bcol) * 4;

    // Q fragments for this warp's tile (held across both chunks)
    uint32_t qa[8][4];
#pragma unroll
    for (int ks = 0; ks < 8; ks++) {
        asm volatile("ldmatrix.sync.aligned.m8n8.x4.shared.b16 {%0,%1,%2,%3}, [%4];"
                     : "=r"(qa[ks][0]), "=r"(qa[ks][1]),
                       "=r"(qa[ks][2]), "=r"(qa[ks][3])
                     : "r"(qAddr0 + ks * 32));
    }

    float o[8][4];
#pragma unroll
    for (int n = 0; n < 8; n++)
#pragma unroll
        for (int r = 0; r < 4; r++) o[n][r] = 0.f;
    float mL = -1e30f, mH = -1e30f, sL = 0.f, sH = 0.f;

    const int src  = (lane & ~3) | (tc >> 1);
    const bool odd = (tc & 1);

#pragma unroll 1
    for (int ch = 0; ch < 2; ch++) {
        // ---- S chunk = Q_tile @ K[ch*112 .. +112]^T : acc[14 n-tiles][4] ----
        float acc[14][4];
#pragma unroll
        for (int j = 0; j < 14; j++)
#pragma unroll
            for (int r = 0; r < 4; r++) acc[j][r] = 0.f;

#pragma unroll
        for (int ks = 0; ks < 8; ks++) {
#pragma unroll
            for (int np = 0; np < 7; np++) {
                uint32_t kb[4];
                uint32_t addr = kAddr0 +
                    (uint32_t)((ch * 7 + np) * 16 * QK_STR) * 4 + ks * 32;
                asm volatile("ldmatrix.sync.aligned.m8n8.x4.shared.b16 {%0,%1,%2,%3}, [%4];"
                             : "=r"(kb[0]), "=r"(kb[1]), "=r"(kb[2]), "=r"(kb[3])
                             : "r"(addr));
                asm volatile(
                    "mma.sync.aligned.m16n8k8.row.col.f32.tf32.tf32.f32 "
                    "{%0,%1,%2,%3}, {%4,%5,%6,%7}, {%8,%9}, {%0,%1,%2,%3};"
                    : "+f"(acc[2*np][0]), "+f"(acc[2*np][1]),
                      "+f"(acc[2*np][2]), "+f"(acc[2*np][3])
                    : "r"(qa[ks][0]), "r"(qa[ks][1]), "r"(qa[ks][2]), "r"(qa[ks][3]),
                      "r"(kb[0]), "r"(kb[1]));
                asm volatile(
                    "mma.sync.aligned.m16n8k8.row.col.f32.tf32.tf32.f32 "
                    "{%0,%1,%2,%3}, {%4,%5,%6,%7}, {%8,%9}, {%0,%1,%2,%3};"
                    : "+f"(acc[2*np+1][0]), "+f"(acc[2*np+1][1]),
                      "+f"(acc[2*np+1][2]), "+f"(acc[2*np+1][3])
                    : "r"(qa[ks][0]), "r"(qa[ks][1]), "r"(qa[ks][2]), "r"(qa[ks][3]),
                      "r"(kb[2]), "r"(kb[3]));
            }
        }

        // ---- mask invalid keys (global n-tile = ch*14 + j; keys >= 196 invalid) ----
        if (ch == 1) {
            if (tc >= 2) {   // n-tile 24: keys 196..199 -> cols 2tc>=4
                acc[10][0] = acc[10][1] = acc[10][2] = acc[10][3] = -1e30f;
            }
#pragma unroll
            for (int j = 11; j < 14; j++) {   // n-tiles 25..27 fully invalid
                acc[j][0] = acc[j][1] = acc[j][2] = acc[j][3] = -1e30f;
            }
        }

        // ---- online softmax update ----
        float mlL = -1e30f, mlH = -1e30f;
#pragma unroll
        for (int j = 0; j < 14; j++) {
            mlL = fmaxf(mlL, fmaxf(acc[j][0], acc[j][1]));
            mlH = fmaxf(mlH, fmaxf(acc[j][2], acc[j][3]));
        }
        mlL = fmaxf(mlL, __shfl_xor_sync(0xffffffffu, mlL, 1));
        mlL = fmaxf(mlL, __shfl_xor_sync(0xffffffffu, mlL, 2));
        mlH = fmaxf(mlH, __shfl_xor_sync(0xffffffffu, mlH, 1));
        mlH = fmaxf(mlH, __shfl_xor_sync(0xffffffffu, mlH, 2));

        float mnL = fmaxf(mL, mlL);
        float mnH = fmaxf(mH, mlH);
        float fL = __expf(mL - mnL);
        float fH = __expf(mH - mnH);
        mL = mnL; mH = mnH;
        sL *= fL; sH *= fH;
#pragma unroll
        for (int n = 0; n < 8; n++) {
            o[n][0] *= fL; o[n][1] *= fL;
            o[n][2] *= fH; o[n][3] *= fH;
        }

#pragma unroll
        for (int j = 0; j < 14; j++) {
            float e0 = __expf(acc[j][0] - mL);
            float e1 = __expf(acc[j][1] - mL);
            float e2 = __expf(acc[j][2] - mH);
            float e3 = __expf(acc[j][3] - mH);
            sL += e0 + e1;
            sH += e2 + e3;
            acc[j][0] = f2tf32f(e0);
            acc[j][1] = f2tf32f(e1);
            acc[j][2] = f2tf32f(e2);
            acc[j][3] = f2tf32f(e3);
        }

        // ---- O += P_chunk @ V_chunk : shuffle-transpose acc -> A fragments ----
#pragma unroll
        for (int kt = 0; kt < 14; kt++) {
            float x0 = __shfl_sync(0xffffffffu, acc[kt][0], src);
            float x1 = __shfl_sync(0xffffffffu, acc[kt][1], src);
            float y0 = __shfl_sync(0xffffffffu, acc[kt][0], src + 2);
            float y1 = __shfl_sync(0xffffffffu, acc[kt][1], src + 2);
            float z0 = __shfl_sync(0xffffffffu, acc[kt][2], src);
            float z1 = __shfl_sync(0xffffffffu, acc[kt][3], src);
            float w0 = __shfl_sync(0xffffffffu, acc[kt][2], src + 2);
            float w1 = __shfl_sync(0xffffffffu, acc[kt][3], src + 2);
            uint32_t a0 = __float_as_uint(odd ? x1 : x0);
            uint32_t a1 = __float_as_uint(odd ? z1 : z0);
            uint32_t a2 = __float_as_uint(odd ? y1 : y0);
            uint32_t a3 = __float_as_uint(odd ? w1 : w0);
#pragma unroll
            for (int np = 0; np < 4; np++) {
                uint32_t vb[4];
                uint32_t addr = vAddr0 + (uint32_t)(np * 16 * VT_STR) * 4 +
                                (uint32_t)(ch * 14 + kt) * 32;
                asm volatile("ldmatrix.sync.aligned.m8n8.x4.shared.b16 {%0,%1,%2,%3}, [%4];"
                             : "=r"(vb[0]), "=r"(vb[1]), "=r"(vb[2]), "=r"(vb[3])
                             : "r"(addr));
                asm volatile(
                    "mma.sync.aligned.m16n8k8.row.col.f32.tf32.tf32.f32 "
                    "{%0,%1,%2,%3}, {%4,%5,%6,%7}, {%8,%9}, {%0,%1,%2,%3};"
                    : "+f"(o[2*np][0]), "+f"(o[2*np][1]),
                      "+f"(o[2*np][2]), "+f"(o[2*np][3])
                    : "r"(a0), "r"(a1), "r"(a2), "r"(a3),
                      "r"(vb[0]), "r"(vb[1]));
                asm volatile(
                    "mma.sync.aligned.m16n8k8.row.col.f32.tf32.tf32.f32 "
                    "{%0,%1,%2,%3}, {%4,%5,%6,%7}, {%8,%9}, {%0,%1,%2,%3};"
                    : "+f"(o[2*np+1][0]), "+f"(o[2*np+1][1]),
                      "+f"(o[2*np+1][2]), "+f"(o[2*np+1][3])
                    : "r"(a0), "r"(a1), "r"(a2), "r"(a3),
                      "r"(vb[2]), "r"(vb[3]));
            }
        }
    }

    // ---- finalize: quad-reduce row sums, normalize, store ----
    sL += __shfl_xor_sync(0xffffffffu, sL, 1);
    sL += __shfl_xor_sync(0xffffffffu, sL, 2);
    sH += __shfl_xor_sync(0xffffffffu, sH, 1);
    sH += __shfl_xor_sync(0xffffffffu, sH, 2);
    const float invL = 1.f / sL;
    const float invH = 1.f / sH;

#pragma unroll
    for (int half = 0; half < 2; half++) {
        int n = tile * 16 + tg + half * 8;
        if (n >= NW) continue;
        int gh = wh * WIN + n / WIN;
        int gw = ww * WIN + n % WIN;
        if (gh >= IMH || gw >= IMW) continue;
        size_t off = (size_t)(b * NTOK + gh * IMW + gw) * C_ + h * HD + 2 * tc;
        float inv = half ? invH : invL;
#pragma unroll
        for (int nn = 0; nn < 8; nn++) {
            float2 o2 = make_float2(f2tf32f(o[nn][2*half] * inv),
                                    f2tf32f(o[nn][2*half + 1] * inv));
            *reinterpret_cast<float2*>(&out[off + nn * 8]) = o2;
        }
    }
}

// ---------------- launcher ----------------
extern "C" void kernel_launch(void* const* d_in, const int* in_sizes, int n_in,
                              void* d_out, int out_size)
{
    (void)in_sizes; (void)n_in; (void)out_size;
    const float* x     = (const float*)d_in[0];
    const float* Wqkv  = (const float*)d_in[1];
    const float* Wproj = (const float*)d_in[2];
    const float* bproj = (const float*)d_in[3];
    float* out = (float*)d_out;

    float *qkv, *attn, *x32, *wqkvT, *wprojT;
    cudaGetSymbolAddress((void**)&qkv,    g_qkv);
    cudaGetSymbolAddress((void**)&attn,   g_attn);
    cudaGetSymbolAddress((void**)&x32,    g_x32);
    cudaGetSymbolAddress((void**)&wqkvT,  g_wqkvT);
    cudaGetSymbolAddress((void**)&wprojT, g_wprojT);

    cudaFuncSetAttribute(attn_mma, cudaFuncAttributeMaxDynamicSharedMemorySize,
                         ATTN2_SMEM_BYTES);
    cudaFuncSetAttribute(gemm_tf32_async, cudaFuncAttributeMaxDynamicSharedMemorySize,
                         GEMM_SMEM_BYTES);

    // prepass
    cvt_kernel<<<1184, 256>>>(x, x32, MROWS * C_ / 4);
    {
        dim3 g(3 * C_ / 32, C_ / 32), blk(32, 8);
        transpose_cvt<<<g, blk>>>(Wqkv, wqkvT, C_, 3 * C_);
    }
    {
        dim3 g(C_ / 32, C_ / 32), blk(32, 8);
        transpose_cvt<<<g, blk>>>(Wproj, wprojT, C_, C_);
    }

    // 1) qkv = x @ Wqkv
    {
        dim3 grid(3 * C_ / 128, MROWS / 128);
        gemm_tf32_async<<<grid, 256, GEMM_SMEM_BYTES>>>(x32, wqkvT, nullptr, qkv,
                                                        MROWS, 3 * C_, C_);
    }
    // 2) windowed attention (tensor cores, balanced/online-softmax)
    {
        dim3 grid(BATCH * NWINS * NH);
        attn_mma<<<grid, ATTN_THREADS, ATTN2_SMEM_BYTES>>>(qkv, attn);
    }
    // 3) out = attn @ Wproj + bproj
    {
        dim3 grid(C_ / 128, MROWS / 128);
        gemm_tf32_async<<<grid, 256, GEMM_SMEM_BYTES>>>(attn, wprojT, bproj, out,
                                                        MROWS, C_, C_);
    }
}

// round 14
// speedup vs baseline: 1.5384x; 1.0019x over previous
#include <cuda_runtime.h>
#include <cstdint>

// ---------------- problem constants ----------------
#define BATCH 8
#define IMH 80
#define IMW 80
#define C_ 768
#define NH 12
#define HD 64
#define WIN 14
#define NWIN 6
#define NWINS 36
#define NW 196
#define NTOK (IMH*IMW)
#define MROWS (BATCH*NTOK)   // 51200

// scratch
__device__ float g_qkv[(size_t)MROWS * 3 * C_];
__device__ float g_attn[(size_t)MROWS * C_];
__device__ float g_x32[(size_t)MROWS * C_];
__device__ float g_wqkvT[(size_t)3 * C_ * C_];
__device__ float g_wprojT[(size_t)C_ * C_];

__device__ __forceinline__ float f2tf32f(float f) {
    uint32_t r;
    asm("cvt.rna.tf32.f32 %0, %1;" : "=r"(r) : "f"(f));
    return __uint_as_float(r);
}

// ---------------- prepass kernels ----------------
__global__ void cvt_kernel(const float* __restrict__ in, float* __restrict__ out, int n4)
{
    int i = blockIdx.x * blockDim.x + threadIdx.x;
    for (; i < n4; i += gridDim.x * blockDim.x) {
        float4 v = reinterpret_cast<const float4*>(in)[i];
        v.x = f2tf32f(v.x); v.y = f2tf32f(v.y);
        v.z = f2tf32f(v.z); v.w = f2tf32f(v.w);
        reinterpret_cast<float4*>(out)[i] = v;
    }
}

__global__ void transpose_cvt(const float* __restrict__ in, float* __restrict__ out,
                              int R, int Cc)
{
    __shared__ float tile[32][33];
    int x = blockIdx.x * 32 + threadIdx.x;
    int y0 = blockIdx.y * 32;
#pragma unroll
    for (int j = 0; j < 32; j += 8)
        tile[threadIdx.y + j][threadIdx.x] = in[(size_t)(y0 + threadIdx.y + j) * Cc + x];
    __syncthreads();
    int ox = blockIdx.y * 32 + threadIdx.x;
    int oy0 = blockIdx.x * 32;
#pragma unroll
    for (int j = 0; j < 32; j += 8)
        out[(size_t)(oy0 + threadIdx.y + j) * R + ox] =
            f2tf32f(tile[threadIdx.x][threadIdx.y + j]);
}

// ---------------- tf32 mma GEMM: 3-stage cp.async + ldmatrix ----------------
// C[M,N] = A[M,K] @ Bt[N,K]^T (+bias). BM=BN=128, BK=32.
// 3 smem stages, prefetch distance 2, ONE __syncthreads per k-tile.
#define BK 32
#define LDT 36
#define TILE_FLOATS (128 * LDT)
#define STAGE_FLOATS (2 * TILE_FLOATS)
#define STAGE_BYTES (STAGE_FLOATS * 4)        // 36864
#define GEMM_STAGES 3
#define GEMM_SMEM_BYTES (GEMM_STAGES * STAGE_BYTES)   // 110592

__device__ __forceinline__ void cp_async16(uint32_t smem_addr, const float* gptr) {
    asm volatile("cp.async.cg.shared.global [%0], [%1], 16;"
                 :: "r"(smem_addr), "l"(gptr));
}

__global__ void __launch_bounds__(256, 2) gemm_tf32_async(
    const float* __restrict__ A, const float* __restrict__ Bt,
    const float* __restrict__ bias, float* __restrict__ C,
    int M, int N, int K)
{
    extern __shared__ float smem[];
    const uint32_t smem_base = (uint32_t)__cvta_generic_to_shared(smem);

    const int tid  = threadIdx.x;
    const int warp = tid >> 5;
    const int lane = tid & 31;
    const int wm = warp & 1;
    const int wn = warp >> 1;
    const int bm = blockIdx.y * 128;
    const int bn = blockIdx.x * 128;

    const int aRow = wm * 64 + (lane & 15);
    const int aCol = (lane >> 4) * 4;
    const int bRow = wn * 32 + (lane & 7) + ((lane & 16) ? 8 : 0);
    const int bCol = (lane & 8) ? 4 : 0;

    float acc[4][4][4];
#pragma unroll
    for (int i = 0; i < 4; i++)
#pragma unroll
        for (int j = 0; j < 4; j++)
#pragma unroll
            for (int r = 0; r < 4; r++) acc[i][j][r] = 0.f;

    const int NT = K / BK;

    auto issue_stage = [&](int t, int s) {
        const float* Ag = A + (size_t)bm * K + t * BK;
        const float* Bg = Bt + (size_t)bn * K + t * BK;
        uint32_t as = smem_base + s * STAGE_BYTES;
        uint32_t bs = as + TILE_FLOATS * 4;
#pragma unroll
        for (int i = 0; i < 4; i++) {
            int c   = tid + 256 * i;
            int row = c >> 3;
            int kc  = (c & 7) * 4;
            uint32_t doff = (uint32_t)(row * LDT + kc) * 4;
            cp_async16(as + doff, Ag + (size_t)row * K + kc);
            cp_async16(bs + doff, Bg + (size_t)row * K + kc);
        }
        asm volatile("cp.async.commit_group;");
    };

    // prologue: two tiles in flight
    issue_stage(0, 0);
    issue_stage(1, 1);

    for (int t = 0; t < NT; t++) {
        // wait until tile t's group is complete (per-thread), then barrier:
        // after the barrier, tile t is visible to all AND every warp has
        // finished compute(t-1), so stage (t+2)%3 is free to refill.
        if (t + 1 < NT) asm volatile("cp.async.wait_group 1;");
        else            asm volatile("cp.async.wait_group 0;");
        __syncthreads();

        if (t + 2 < NT) issue_stage(t + 2, (t + 2) % GEMM_STAGES);

        const int s = t % GEMM_STAGES;
        uint32_t as = smem_base + s * STAGE_BYTES;
        uint32_t bs = as + TILE_FLOATS * 4;

#pragma unroll
        for (int ks = 0; ks < 4; ks++) {
            uint32_t af[4][4];
#pragma unroll
            for (int mi = 0; mi < 4; mi++) {
                uint32_t addr = as + (uint32_t)((aRow + mi * 16) * LDT + aCol + ks * 8) * 4;
                asm volatile("ldmatrix.sync.aligned.m8n8.x4.shared.b16 {%0,%1,%2,%3}, [%4];"
                             : "=r"(af[mi][0]), "=r"(af[mi][1]),
                               "=r"(af[mi][2]), "=r"(af[mi][3])
                             : "r"(addr));
            }
            uint32_t bf[2][4];
#pragma unroll
            for (int np = 0; np < 2; np++) {
                uint32_t addr = bs + (uint32_t)((bRow + np * 16) * LDT + bCol + ks * 8) * 4;
                asm volatile("ldmatrix.sync.aligned.m8n8.x4.shared.b16 {%0,%1,%2,%3}, [%4];"
                             : "=r"(bf[np][0]), "=r"(bf[np][1]),
                               "=r"(bf[np][2]), "=r"(bf[np][3])
                             : "r"(addr));
            }
#pragma unroll
            for (int mi = 0; mi < 4; mi++) {
#pragma unroll
                for (int np = 0; np < 2; np++) {
                    asm volatile(
                        "mma.sync.aligned.m16n8k8.row.col.f32.tf32.tf32.f32 "
                        "{%0,%1,%2,%3}, {%4,%5,%6,%7}, {%8,%9}, {%0,%1,%2,%3};"
                        : "+f"(acc[mi][2*np][0]), "+f"(acc[mi][2*np][1]),
                          "+f"(acc[mi][2*np][2]), "+f"(acc[mi][2*np][3])
                        : "r"(af[mi][0]), "r"(af[mi][1]), "r"(af[mi][2]), "r"(af[mi][3]),
                          "r"(bf[np][0]), "r"(bf[np][1]));
                    asm volatile(
                        "mma.sync.aligned.m16n8k8.row.col.f32.tf32.tf32.f32 "
                        "{%0,%1,%2,%3}, {%4,%5,%6,%7}, {%8,%9}, {%0,%1,%2,%3};"
                        : "+f"(acc[mi][2*np+1][0]), "+f"(acc[mi][2*np+1][1]),
                          "+f"(acc[mi][2*np+1][2]), "+f"(acc[mi][2*np+1][3])
                        : "r"(af[mi][0]), "r"(af[mi][1]), "r"(af[mi][2]), "r"(af[mi][3]),
                          "r"(bf[np][2]), "r"(bf[np][3]));
                }
            }
        }
        // no second barrier: next iteration's top barrier provides the
        // WAR guard before stage reuse.
    }

    const int tg = lane >> 2;
    const int tc = lane & 3;
#pragma unroll
    for (int mi = 0; mi < 4; mi++) {
        int row = bm + wm * 64 + mi * 16 + tg;
#pragma unroll
        for (int ni = 0; ni < 4; ni++) {
            int col = bn + wn * 32 + ni * 8 + tc * 2;
            float b0 = bias ? bias[col]     : 0.f;
            float b1 = bias ? bias[col + 1] : 0.f;
            float2 v0 = make_float2(acc[mi][ni][0] + b0, acc[mi][ni][1] + b1);
            float2 v1 = make_float2(acc[mi][ni][2] + b0, acc[mi][ni][3] + b1);
            *reinterpret_cast<float2*>(&C[(size_t)row * N + col])       = v0;
            *reinterpret_cast<float2*>(&C[(size_t)(row + 8) * N + col]) = v1;
        }
    }
}

// ---------------- tensor-core windowed attention (R7-best, unchanged) ----------------
#define NROWP 224
#define QK_STR 68
#define VT_STR 228
#define ATTN_THREADS 416
#define ATTN2_FLOATS (2 * NROWP * QK_STR + HD * VT_STR)
#define ATTN2_SMEM_BYTES (ATTN2_FLOATS * 4)

__global__ void __launch_bounds__(ATTN_THREADS, 1) attn_mma(
    const float* __restrict__ qkv, float* __restrict__ out)
{
    extern __shared__ float sm[];
    float* Qs = sm;
    float* Ks = Qs + NROWP * QK_STR;
    float* VT = Ks + NROWP * QK_STR;
    const uint32_t smem_u32 = (uint32_t)__cvta_generic_to_shared(sm);
    const uint32_t Koff = NROWP * QK_STR * 4;
    const uint32_t Voff = 2 * NROWP * QK_STR * 4;

    const int bid = blockIdx.x;
    const int h = bid % NH;
    const int l = (bid / NH) % NWINS;
    const int b = bid / (NH * NWINS);
    const int wh = l / NWIN, ww = l % NWIN;

    const int tid  = threadIdx.x;
    const int warp = tid >> 5;
    const int lane = tid & 31;
    const int tg   = lane >> 2;
    const int tc   = lane & 3;

    for (int idx = tid; idx < NROWP * HD; idx += ATTN_THREADS) {
        int n = idx >> 6, d = idx & 63;
        float q = 0.f, k = 0.f, v = 0.f;
        if (n < NW) {
            int gh = wh * WIN + (n / WIN);
            int gw = ww * WIN + (n % WIN);
            if (gh < IMH && gw < IMW) {
                size_t off = (size_t)(b * NTOK + gh * IMW + gw) * (3 * C_) + h * HD + d;
                q = qkv[off];
                k = qkv[off + C_];
                v = qkv[off + 2 * C_];
            }
        }
        Qs[n * QK_STR + d] = f2tf32f(q * 0.125f);
        Ks[n * QK_STR + d] = f2tf32f(k);
        VT[d * VT_STR + n] = f2tf32f(v);
    }
    __syncthreads();

    const int tile = warp;

    const uint32_t qAddr0 = smem_u32 +
        (uint32_t)((tile * 16 + (lane & 15)) * QK_STR + (lane >> 4) * 4) * 4;
    const int brow = (lane & 7) + ((lane & 16) ? 8 : 0);
    const int bcol = (lane & 8) ? 4 : 0;
    const uint32_t kAddr0 = smem_u32 + Koff + (uint32_t)(brow * QK_STR + bcol) * 4;
    const uint32_t vAddr0 = smem_u32 + Voff + (uint32_t)(brow * VT_STR + bcol) * 4;

    uint32_t qa[8][4];
#pragma unroll
    for (int ks = 0; ks < 8; ks++) {
        asm volatile("ldmatrix.sync.aligned.m8n8.x4.shared.b16 {%0,%1,%2,%3}, [%4];"
                     : "=r"(qa[ks][0]), "=r"(qa[ks][1]),
                       "=r"(qa[ks][2]), "=r"(qa[ks][3])
                     : "r"(qAddr0 + ks * 32));
    }

    float o[8][4];
#pragma unroll
    for (int n = 0; n < 8; n++)
#pragma unroll
        for (int r = 0; r < 4; r++) o[n][r] = 0.f;
    float mL = -1e30f, mH = -1e30f, sL = 0.f, sH = 0.f;

    const int src  = (lane & ~3) | (tc >> 1);
    const bool odd = (tc & 1);

#pragma unroll 1
    for (int ch = 0; ch < 2; ch++) {
        float acc[14][4];
#pragma unroll
        for (int j = 0; j < 14; j++)
#pragma unroll
            for (int r = 0; r < 4; r++) acc[j][r] = 0.f;

#pragma unroll
        for (int ks = 0; ks < 8; ks++) {
#pragma unroll
            for (int np = 0; np < 7; np++) {
                uint32_t kb[4];
                uint32_t addr = kAddr0 +
                    (uint32_t)((ch * 7 + np) * 16 * QK_STR) * 4 + ks * 32;
                asm volatile("ldmatrix.sync.aligned.m8n8.x4.shared.b16 {%0,%1,%2,%3}, [%4];"
                             : "=r"(kb[0]), "=r"(kb[1]), "=r"(kb[2]), "=r"(kb[3])
                             : "r"(addr));
                asm volatile(
                    "mma.sync.aligned.m16n8k8.row.col.f32.tf32.tf32.f32 "
                    "{%0,%1,%2,%3}, {%4,%5,%6,%7}, {%8,%9}, {%0,%1,%2,%3};"
                    : "+f"(acc[2*np][0]), "+f"(acc[2*np][1]),
                      "+f"(acc[2*np][2]), "+f"(acc[2*np][3])
                    : "r"(qa[ks][0]), "r"(qa[ks][1]), "r"(qa[ks][2]), "r"(qa[ks][3]),
                      "r"(kb[0]), "r"(kb[1]));
                asm volatile(
                    "mma.sync.aligned.m16n8k8.row.col.f32.tf32.tf32.f32 "
                    "{%0,%1,%2,%3}, {%4,%5,%6,%7}, {%8,%9}, {%0,%1,%2,%3};"
                    : "+f"(acc[2*np+1][0]), "+f"(acc[2*np+1][1]),
                      "+f"(acc[2*np+1][2]), "+f"(acc[2*np+1][3])
                    : "r"(qa[ks][0]), "r"(qa[ks][1]), "r"(qa[ks][2]), "r"(qa[ks][3]),
                      "r"(kb[2]), "r"(kb[3]));
            }
        }

        if (ch == 1) {
            if (tc >= 2) {
                acc[10][0] = acc[10][1] = acc[10][2] = acc[10][3] = -1e30f;
            }
#pragma unroll
            for (int j = 11; j < 14; j++) {
                acc[j][0] = acc[j][1] = acc[j][2] = acc[j][3] = -1e30f;
            }
        }

        float mlL = -1e30f, mlH = -1e30f;
#pragma unroll
        for (int j = 0; j < 14; j++) {
            mlL = fmaxf(mlL, fmaxf(acc[j][0], acc[j][1]));
            mlH = fmaxf(mlH, fmaxf(acc[j][2], acc[j][3]));
        }
        mlL = fmaxf(mlL, __shfl_xor_sync(0xffffffffu, mlL, 1));
        mlL = fmaxf(mlL, __shfl_xor_sync(0xffffffffu, mlL, 2));
        mlH = fmaxf(mlH, __shfl_xor_sync(0xffffffffu, mlH, 1));
        mlH = fmaxf(mlH, __shfl_xor_sync(0xffffffffu, mlH, 2));

        float mnL = fmaxf(mL, mlL);
        float mnH = fmaxf(mH, mlH);
        float fL = __expf(mL - mnL);
        float fH = __expf(mH - mnH);
        mL = mnL; mH = mnH;
        sL *= fL; sH *= fH;
#pragma unroll
        for (int n = 0; n < 8; n++) {
            o[n][0] *= fL; o[n][1] *= fL;
            o[n][2] *= fH; o[n][3] *= fH;
        }

#pragma unroll
        for (int j = 0; j < 14; j++) {
            float e0 = __expf(acc[j][0] - mL);
            float e1 = __expf(acc[j][1] - mL);
            float e2 = __expf(acc[j][2] - mH);
            float e3 = __expf(acc[j][3] - mH);
            sL += e0 + e1;
            sH += e2 + e3;
            acc[j][0] = f2tf32f(e0);
            acc[j][1] = f2tf32f(e1);
            acc[j][2] = f2tf32f(e2);
            acc[j][3] = f2tf32f(e3);
        }

#pragma unroll
        for (int kt = 0; kt < 14; kt++) {
            float x0 = __shfl_sync(0xffffffffu, acc[kt][0], src);
            float x1 = __shfl_sync(0xffffffffu, acc[kt][1], src);
            float y0 = __shfl_sync(0xffffffffu, acc[kt][0], src + 2);
            float y1 = __shfl_sync(0xffffffffu, acc[kt][1], src + 2);
            float z0 = __shfl_sync(0xffffffffu, acc[kt][2], src);
            float z1 = __shfl_sync(0xffffffffu, acc[kt][3], src);
            float w0 = __shfl_sync(0xffffffffu, acc[kt][2], src + 2);
            float w1 = __shfl_sync(0xffffffffu, acc[kt][3], src + 2);
            uint32_t a0 = __float_as_uint(odd ? x1 : x0);
            uint32_t a1 = __float_as_uint(odd ? z1 : z0);
            uint32_t a2 = __float_as_uint(odd ? y1 : y0);
            uint32_t a3 = __float_as_uint(odd ? w1 : w0);
#pragma unroll
            for (int np = 0; np < 4; np++) {
                uint32_t vb[4];
                uint32_t addr = vAddr0 + (uint32_t)(np * 16 * VT_STR) * 4 +
                                (uint32_t)(ch * 14 + kt) * 32;
                asm volatile("ldmatrix.sync.aligned.m8n8.x4.shared.b16 {%0,%1,%2,%3}, [%4];"
                             : "=r"(vb[0]), "=r"(vb[1]), "=r"(vb[2]), "=r"(vb[3])
                             : "r"(addr));
                asm volatile(
                    "mma.sync.aligned.m16n8k8.row.col.f32.tf32.tf32.f32 "
                    "{%0,%1,%2,%3}, {%4,%5,%6,%7}, {%8,%9}, {%0,%1,%2,%3};"
                    : "+f"(o[2*np][0]), "+f"(o[2*np][1]),
                      "+f"(o[2*np][2]), "+f"(o[2*np][3])
                    : "r"(a0), "r"(a1), "r"(a2), "r"(a3),
                      "r"(vb[0]), "r"(vb[1]));
                asm volatile(
                    "mma.sync.aligned.m16n8k8.row.col.f32.tf32.tf32.f32 "
                    "{%0,%1,%2,%3}, {%4,%5,%6,%7}, {%8,%9}, {%0,%1,%2,%3};"
                    : "+f"(o[2*np+1][0]), "+f"(o[2*np+1][1]),
                      "+f"(o[2*np+1][2]), "+f"(o[2*np+1][3])
                    : "r"(a0), "r"(a1), "r"(a2), "r"(a3),
                      "r"(vb[2]), "r"(vb[3]));
            }
        }
    }

    sL += __shfl_xor_sync(0xffffffffu, sL, 1);
    sL += __shfl_xor_sync(0xffffffffu, sL, 2);
    sH += __shfl_xor_sync(0xffffffffu, sH, 1);
    sH += __shfl_xor_sync(0xffffffffu, sH, 2);
    const float invL = 1.f / sL;
    const float invH = 1.f / sH;

#pragma unroll
    for (int half = 0; half < 2; half++) {
        int n = tile * 16 + tg + half * 8;
        if (n >= NW) continue;
        int gh = wh * WIN + n / WIN;
        int gw = ww * WIN + n % WIN;
        if (gh >= IMH || gw >= IMW) continue;
        size_t off = (size_t)(b * NTOK + gh * IMW + gw) * C_ + h * HD + 2 * tc;
        float inv = half ? invH : invL;
#pragma unroll
        for (int nn = 0; nn < 8; nn++) {
            float2 o2 = make_float2(f2tf32f(o[nn][2*half] * inv),
                                    f2tf32f(o[nn][2*half + 1] * inv));
            *reinterpret_cast<float2*>(&out[off + nn * 8]) = o2;
        }
    }
}

// ---------------- launcher ----------------
extern "C" void kernel_launch(void* const* d_in, const int* in_sizes, int n_in,
                              void* d_out, int out_size)
{
    (void)in_sizes; (void)n_in; (void)out_size;
    const float* x     = (const float*)d_in[0];
    const float* Wqkv  = (const float*)d_in[1];
    const float* Wproj = (const float*)d_in[2];
    const float* bproj = (const float*)d_in[3];
    float* out = (float*)d_out;

    float *qkv, *attn, *x32, *wqkvT, *wprojT;
    cudaGetSymbolAddress((void**)&qkv,    g_qkv);
    cudaGetSymbolAddress((void**)&attn,   g_attn);
    cudaGetSymbolAddress((void**)&x32,    g_x32);
    cudaGetSymbolAddress((void**)&wqkvT,  g_wqkvT);
    cudaGetSymbolAddress((void**)&wprojT, g_wprojT);

    cudaFuncSetAttribute(attn_mma, cudaFuncAttributeMaxDynamicSharedMemorySize,
                         ATTN2_SMEM_BYTES);
    cudaFuncSetAttribute(gemm_tf32_async, cudaFuncAttributeMaxDynamicSharedMemorySize,
                         GEMM_SMEM_BYTES);

    // prepass
    cvt_kernel<<<1184, 256>>>(x, x32, MROWS * C_ / 4);
    {
        dim3 g(3 * C_ / 32, C_ / 32), blk(32, 8);
        transpose_cvt<<<g, blk>>>(Wqkv, wqkvT, C_, 3 * C_);
    }
    {
        dim3 g(C_ / 32, C_ / 32), blk(32, 8);
        transpose_cvt<<<g, blk>>>(Wproj, wprojT, C_, C_);
    }

    // 1) qkv = x @ Wqkv
    {
        dim3 grid(3 * C_ / 128, MROWS / 128);
        gemm_tf32_async<<<grid, 256, GEMM_SMEM_BYTES>>>(x32, wqkvT, nullptr, qkv,
                                                        MROWS, 3 * C_, C_);
    }
    // 2) windowed attention
    {
        dim3 grid(BATCH * NWINS * NH);
        attn_mma<<<grid, ATTN_THREADS, ATTN2_SMEM_BYTES>>>(qkv, attn);
    }
    // 3) out = attn @ Wproj + bproj
    {
        dim3 grid(C_ / 128, MROWS / 128);
        gemm_tf32_async<<<grid, 256, GEMM_SMEM_BYTES>>>(attn, wprojT, bproj, out,
                                                        MROWS, C_, C_);
    }
}